// round 1
// baseline (speedup 1.0000x reference)
#include <cuda_runtime.h>

#define D_MODEL 1024
#define NH      16
#define DH      64
#define BATCH   2
#define SEQ     2048
#define MTOT    (BATCH*SEQ)   // 4096

// ---------------- scratch (allocation-free) ----------------
__device__ float g_qh[(size_t)BATCH*NH*SEQ*DH];     // [b,h,s,dh]
__device__ float g_kh[(size_t)BATCH*NH*SEQ*DH];
__device__ float g_vh[(size_t)BATCH*NH*SEQ*DH];
__device__ float g_attn[(size_t)BATCH*SEQ*D_MODEL]; // [b,s,h*dh]

// ================= GEMM mainloop: C[128,128] += X[128,K] * W[128,K]^T =================
// blockDim=256, BK=16, 8x8 microtile per thread, register double-buffer on global loads.
__device__ __forceinline__ void gemm_mainloop(
    const float* __restrict__ X, const float* __restrict__ W,
    float (*As)[128], float (*Bs)[128], float acc[8][8], int m0, int n0)
{
    const int tid = threadIdx.x;
    const int lr = tid >> 2;          // 0..63
    const int lc = (tid & 3) << 2;    // 0,4,8,12
    const int ty = tid >> 4;
    const int tx = tid & 15;

    const float* Ap = X + (size_t)(m0 + lr) * D_MODEL + lc;
    const float* Bp = W + (size_t)(n0 + lr) * D_MODEL + lc;

    float4 a0 = *(const float4*)Ap;
    float4 a1 = *(const float4*)(Ap + (size_t)64 * D_MODEL);
    float4 b0 = *(const float4*)Bp;
    float4 b1 = *(const float4*)(Bp + (size_t)64 * D_MODEL);

    const int NKT = D_MODEL / 16;
    for (int kt = 0; kt < NKT; ++kt) {
        __syncthreads();
        As[lc+0][lr]    = a0.x; As[lc+1][lr]    = a0.y; As[lc+2][lr]    = a0.z; As[lc+3][lr]    = a0.w;
        As[lc+0][lr+64] = a1.x; As[lc+1][lr+64] = a1.y; As[lc+2][lr+64] = a1.z; As[lc+3][lr+64] = a1.w;
        Bs[lc+0][lr]    = b0.x; Bs[lc+1][lr]    = b0.y; Bs[lc+2][lr]    = b0.z; Bs[lc+3][lr]    = b0.w;
        Bs[lc+0][lr+64] = b1.x; Bs[lc+1][lr+64] = b1.y; Bs[lc+2][lr+64] = b1.z; Bs[lc+3][lr+64] = b1.w;
        __syncthreads();
        if (kt + 1 < NKT) {
            const float* Ap2 = Ap + (kt + 1) * 16;
            const float* Bp2 = Bp + (kt + 1) * 16;
            a0 = *(const float4*)Ap2;
            a1 = *(const float4*)(Ap2 + (size_t)64 * D_MODEL);
            b0 = *(const float4*)Bp2;
            b1 = *(const float4*)(Bp2 + (size_t)64 * D_MODEL);
        }
#pragma unroll
        for (int kk = 0; kk < 16; ++kk) {
            float4 av0 = *(const float4*)&As[kk][ty*8];
            float4 av1 = *(const float4*)&As[kk][ty*8+4];
            float4 bv0 = *(const float4*)&Bs[kk][tx*8];
            float4 bv1 = *(const float4*)&Bs[kk][tx*8+4];
            float a[8]  = {av0.x,av0.y,av0.z,av0.w,av1.x,av1.y,av1.z,av1.w};
            float bb[8] = {bv0.x,bv0.y,bv0.z,bv0.w,bv1.x,bv1.y,bv1.z,bv1.w};
#pragma unroll
            for (int i = 0; i < 8; ++i)
#pragma unroll
                for (int j = 0; j < 8; ++j)
                    acc[i][j] = fmaf(a[i], bb[j], acc[i][j]);
        }
    }
}

// ================= Projection GEMM (Q/K/V fused via grid.z), scatter to head layout =================
__global__ __launch_bounds__(256) void proj_gemm(
    const float* __restrict__ xq, const float* __restrict__ xk, const float* __restrict__ xv,
    const float* __restrict__ Wq, const float* __restrict__ Wk, const float* __restrict__ Wv,
    const float* __restrict__ bq, const float* __restrict__ bk, const float* __restrict__ bv)
{
    __shared__ float As[16][128];
    __shared__ float Bs[16][128];
    const int z = blockIdx.z;
    const float* X    = (z == 0) ? xq : (z == 1) ? xk : xv;
    const float* W    = (z == 0) ? Wq : (z == 1) ? Wk : Wv;
    const float* bias = (z == 0) ? bq : (z == 1) ? bk : bv;
    float* out        = (z == 0) ? g_qh : (z == 1) ? g_kh : g_vh;

    const int m0 = blockIdx.y * 128, n0 = blockIdx.x * 128;
    float acc[8][8] = {};
    gemm_mainloop(X, W, As, Bs, acc, m0, n0);

    const int tx = threadIdx.x & 15, ty = threadIdx.x >> 4;
    float bf[8];
#pragma unroll
    for (int j = 0; j < 8; ++j) bf[j] = bias[n0 + tx*8 + j];
#pragma unroll
    for (int i = 0; i < 8; ++i) {
        const int m  = m0 + ty*8 + i;
        const int bi = m >> 11;            // / SEQ
        const int s  = m & (SEQ - 1);
#pragma unroll
        for (int j = 0; j < 8; ++j) {
            const int n = n0 + tx*8 + j;
            const int h = n >> 6, d = n & 63;
            out[(((size_t)bi*NH + h)*SEQ + s)*DH + d] = acc[i][j] + bf[j];
        }
    }
}

// ================= Output GEMM: d_out = g_attn @ Wo^T + bo =================
__global__ __launch_bounds__(256) void out_gemm(
    const float* __restrict__ Wo, const float* __restrict__ bo, float* __restrict__ out)
{
    __shared__ float As[16][128];
    __shared__ float Bs[16][128];
    const int m0 = blockIdx.y * 128, n0 = blockIdx.x * 128;
    float acc[8][8] = {};
    gemm_mainloop(g_attn, Wo, As, Bs, acc, m0, n0);

    const int tx = threadIdx.x & 15, ty = threadIdx.x >> 4;
    float bf[8];
#pragma unroll
    for (int j = 0; j < 8; ++j) bf[j] = bo[n0 + tx*8 + j];
#pragma unroll
    for (int i = 0; i < 8; ++i)
#pragma unroll
        for (int j = 0; j < 8; ++j)
            out[(size_t)(m0 + ty*8 + i)*D_MODEL + n0 + tx*8 + j] = acc[i][j] + bf[j];
}

// ================= Flash attention: one block per (b, h, 64-row q-tile) =================
// smem: Qt[64d][65] (transposed), Kt[64d][65] (transposed, reused as P[64i][65]), Vs[64j][64d]
#define ATTN_SMEM_FLOATS (65*64*2 + 64*64)

__global__ __launch_bounds__(256) void attn_kernel(const int* __restrict__ mask)
{
    extern __shared__ float sm[];
    float* Qt = sm;
    float* Kt = sm + 65*64;
    float* Vs = sm + 65*64*2;

    const int qt = blockIdx.x, h = blockIdx.y, b = blockIdx.z;
    const int tid = threadIdx.x;
    const int tx = tid & 15, ty = tid >> 4;

    const size_t bh = ((size_t)b*NH + h) * SEQ * DH;
    const float* Qg = g_qh + bh + (size_t)qt*64*DH;
    const float* Kg = g_kh + bh;
    const float* Vg = g_vh + bh;

    for (int idx = tid; idx < 64*DH; idx += 256) {
        int i = idx >> 6, d = idx & 63;
        Qt[d*65 + i] = Qg[(size_t)i*DH + d];
    }

    float m_i[4], l_i[4], o[4][4];
#pragma unroll
    for (int ii = 0; ii < 4; ++ii) {
        m_i[ii] = -1e30f; l_i[ii] = 0.f;
#pragma unroll
        for (int dd = 0; dd < 4; ++dd) o[ii][dd] = 0.f;
    }

    const int* mbase = mask + ((size_t)b*SEQ + qt*64 + ty*4) * SEQ + tx*4;

    for (int kt = 0; kt < SEQ/64; ++kt) {
        __syncthreads();                       // previous PV done reading Kt(P)/Vs
        const float* Kgt = Kg + (size_t)kt*64*DH;
        const float* Vgt = Vg + (size_t)kt*64*DH;
        for (int idx = tid; idx < 64*DH; idx += 256) {
            int j = idx >> 6, d = idx & 63;
            Kt[d*65 + j] = Kgt[idx];           // idx = j*64 + d
            Vs[idx]      = Vgt[idx];
        }
        __syncthreads();

        // scores S = Q K^T
        float sc[4][4];
#pragma unroll
        for (int ii = 0; ii < 4; ++ii)
#pragma unroll
            for (int jj = 0; jj < 4; ++jj) sc[ii][jj] = 0.f;

        for (int d = 0; d < DH; ++d) {
            float qa[4], kb[4];
#pragma unroll
            for (int ii = 0; ii < 4; ++ii) qa[ii] = Qt[d*65 + ty*4 + ii];
#pragma unroll
            for (int jj = 0; jj < 4; ++jj) kb[jj] = Kt[d*65 + tx*4 + jj];
#pragma unroll
            for (int ii = 0; ii < 4; ++ii)
#pragma unroll
                for (int jj = 0; jj < 4; ++jj)
                    sc[ii][jj] = fmaf(qa[ii], kb[jj], sc[ii][jj]);
        }

        // scale + mask (reference: masked -> exactly -10000.0)
#pragma unroll
        for (int ii = 0; ii < 4; ++ii) {
            int4 mm = *(const int4*)(mbase + (size_t)ii*SEQ + kt*64);
            sc[ii][0] = mm.x ? sc[ii][0]*0.125f : -10000.f;
            sc[ii][1] = mm.y ? sc[ii][1]*0.125f : -10000.f;
            sc[ii][2] = mm.z ? sc[ii][2]*0.125f : -10000.f;
            sc[ii][3] = mm.w ? sc[ii][3]*0.125f : -10000.f;
        }

        // online softmax (row owned by the 16 tx lanes of a half-warp)
#pragma unroll
        for (int ii = 0; ii < 4; ++ii) {
            float mx = fmaxf(fmaxf(sc[ii][0], sc[ii][1]), fmaxf(sc[ii][2], sc[ii][3]));
#pragma unroll
            for (int off = 1; off < 16; off <<= 1)
                mx = fmaxf(mx, __shfl_xor_sync(0xffffffffu, mx, off));
            float mn = fmaxf(m_i[ii], mx);
            float sum = 0.f;
#pragma unroll
            for (int jj = 0; jj < 4; ++jj) { sc[ii][jj] = __expf(sc[ii][jj] - mn); sum += sc[ii][jj]; }
#pragma unroll
            for (int off = 1; off < 16; off <<= 1)
                sum += __shfl_xor_sync(0xffffffffu, sum, off);
            float corr = __expf(m_i[ii] - mn);
            l_i[ii] = l_i[ii]*corr + sum;
            m_i[ii] = mn;
#pragma unroll
            for (int dd = 0; dd < 4; ++dd) o[ii][dd] *= corr;
        }

        __syncthreads();                       // everyone done reading Kt
#pragma unroll
        for (int ii = 0; ii < 4; ++ii)
#pragma unroll
            for (int jj = 0; jj < 4; ++jj)
                Kt[(ty*4+ii)*65 + tx*4 + jj] = sc[ii][jj];   // P overlay
        __syncthreads();

        // O += P V
        for (int j = 0; j < 64; ++j) {
            float pv[4], vv[4];
#pragma unroll
            for (int ii = 0; ii < 4; ++ii) pv[ii] = Kt[(ty*4+ii)*65 + j];
#pragma unroll
            for (int dd = 0; dd < 4; ++dd) vv[dd] = Vs[j*64 + tx*4 + dd];
#pragma unroll
            for (int ii = 0; ii < 4; ++ii)
#pragma unroll
                for (int dd = 0; dd < 4; ++dd)
                    o[ii][dd] = fmaf(pv[ii], vv[dd], o[ii][dd]);
        }
    }

    // normalize + write back to [b, s, h*dh]
#pragma unroll
    for (int ii = 0; ii < 4; ++ii) {
        float inv = 1.f / l_i[ii];
        size_t row = (size_t)b*SEQ + qt*64 + ty*4 + ii;
#pragma unroll
        for (int dd = 0; dd < 4; ++dd)
            g_attn[row*D_MODEL + h*DH + tx*4 + dd] = o[ii][dd] * inv;
    }
}

// ================= launch =================
extern "C" void kernel_launch(void* const* d_in, const int* in_sizes, int n_in,
                              void* d_out, int out_size)
{
    (void)in_sizes; (void)n_in; (void)out_size;
    const float* q  = (const float*)d_in[0];
    const float* k  = (const float*)d_in[1];
    const float* v  = (const float*)d_in[2];
    const int* mask = (const int*)d_in[3];
    const float* Wq = (const float*)d_in[4];
    const float* bq = (const float*)d_in[5];
    const float* Wk = (const float*)d_in[6];
    const float* bk = (const float*)d_in[7];
    const float* Wv = (const float*)d_in[8];
    const float* bv = (const float*)d_in[9];
    const float* Wo = (const float*)d_in[10];
    const float* bo = (const float*)d_in[11];
    float* out = (float*)d_out;

    proj_gemm<<<dim3(D_MODEL/128, MTOT/128, 3), 256>>>(q, k, v, Wq, Wk, Wv, bq, bk, bv);

    const int attn_smem = ATTN_SMEM_FLOATS * (int)sizeof(float);
    cudaFuncSetAttribute(attn_kernel, cudaFuncAttributeMaxDynamicSharedMemorySize, attn_smem);
    attn_kernel<<<dim3(SEQ/64, NH, BATCH), 256, attn_smem>>>(mask);

    out_gemm<<<dim3(D_MODEL/128, MTOT/128, 1), 256>>>(Wo, bo, out);
}

// round 3
// speedup vs baseline: 2.5084x; 2.5084x over previous
#include <cuda_runtime.h>
#include <cstdint>

#define D_MODEL 1024
#define NH      16
#define DH      64
#define BATCH   2
#define SEQ     2048
#define MTOT    (BATCH*SEQ)   // 4096
#define KDIM    1024

// ---------------- scratch (allocation-free) ----------------
__device__ float g_qh[(size_t)BATCH*NH*SEQ*DH];     // [b,h,s,dh]
__device__ float g_kh[(size_t)BATCH*NH*SEQ*DH];
__device__ float g_vh[(size_t)BATCH*NH*SEQ*DH];
__device__ float g_attn[(size_t)BATCH*SEQ*D_MODEL]; // [b,s,h*dh]

// =====================================================================
// helpers
// =====================================================================
__device__ __forceinline__ uint32_t f2tf32(float f) {
    uint32_t r;
    asm("cvt.rna.tf32.f32 %0, %1;" : "=r"(r) : "f"(f));
    return r;
}

// D += A(16x8,row) * B(8x8,col)  tf32
__device__ __forceinline__ void mma_tf32(float c[4], const uint32_t a[4], const uint32_t b[2]) {
    asm volatile(
        "mma.sync.aligned.m16n8k8.row.col.f32.tf32.tf32.f32 "
        "{%0,%1,%2,%3}, {%4,%5,%6,%7}, {%8,%9}, {%0,%1,%2,%3};"
        : "+f"(c[0]), "+f"(c[1]), "+f"(c[2]), "+f"(c[3])
        : "r"(a[0]), "r"(a[1]), "r"(a[2]), "r"(a[3]), "r"(b[0]), "r"(b[1]));
}

// =====================================================================
// GEMM: out[M,N] = X[M,K] @ W[N,K]^T + bias  (tf32 mma.sync)
//   BM=128 BN=128 BK=32, 256 thr, warp grid 4(m)x2(n), warp tile 32x64
//   mode 0/1/2 -> scatter to g_qh/g_kh/g_vh head layout; mode 3 -> row-major out
// =====================================================================
#define GBK  32
#define ASTR 36   // BK + 4 pad

__global__ __launch_bounds__(256) void tc_gemm(
    const float* __restrict__ Xin, const float* __restrict__ W,
    const float* __restrict__ bias, float* __restrict__ outp, int mode)
{
    __shared__ uint32_t smA[128*ASTR];
    __shared__ uint32_t smB[128*ASTR];

    const int tid = threadIdx.x, wid = tid >> 5, lane = tid & 31;
    const int g = lane >> 2, tig = lane & 3;
    const int wm = wid >> 1, wn = wid & 1;
    const int m0 = blockIdx.y * 128, n0 = blockIdx.x * 128;

    const float* X = (mode == 3) ? g_attn : Xin;
    float* out = (mode == 0) ? g_qh : (mode == 1) ? g_kh : (mode == 2) ? g_vh : outp;
    const int scatter = (mode < 3);

    // staging map: 4 slots per thread per operand; slot = tid + r*256
    int srow[4], scol;
    scol = (tid & 7) * 4;
#pragma unroll
    for (int r = 0; r < 4; ++r) srow[r] = (tid + r*256) >> 3;

    const float* gA = X + (size_t)m0 * KDIM;
    const float* gB = W + (size_t)n0 * KDIM;

    float4 pa[4], pb[4];
#pragma unroll
    for (int r = 0; r < 4; ++r) {
        pa[r] = *(const float4*)(gA + (size_t)srow[r]*KDIM + scol);
        pb[r] = *(const float4*)(gB + (size_t)srow[r]*KDIM + scol);
    }

    float acc[2][8][4];
#pragma unroll
    for (int mt = 0; mt < 2; ++mt)
#pragma unroll
        for (int nt = 0; nt < 8; ++nt)
#pragma unroll
            for (int i = 0; i < 4; ++i) acc[mt][nt][i] = 0.f;

    const int NKT = KDIM / GBK;   // 32
    for (int kt = 0; kt < NKT; ++kt) {
        __syncthreads();
#pragma unroll
        for (int r = 0; r < 4; ++r) {
            uint32_t* pA = smA + srow[r]*ASTR + scol;
            pA[0]=f2tf32(pa[r].x); pA[1]=f2tf32(pa[r].y); pA[2]=f2tf32(pa[r].z); pA[3]=f2tf32(pa[r].w);
            uint32_t* pB = smB + srow[r]*ASTR + scol;
            pB[0]=f2tf32(pb[r].x); pB[1]=f2tf32(pb[r].y); pB[2]=f2tf32(pb[r].z); pB[3]=f2tf32(pb[r].w);
        }
        __syncthreads();
        if (kt + 1 < NKT) {
            const int k1 = (kt + 1) * GBK;
#pragma unroll
            for (int r = 0; r < 4; ++r) {
                pa[r] = *(const float4*)(gA + (size_t)srow[r]*KDIM + k1 + scol);
                pb[r] = *(const float4*)(gB + (size_t)srow[r]*KDIM + k1 + scol);
            }
        }
#pragma unroll
        for (int ks = 0; ks < 4; ++ks) {
            uint32_t af[2][4];
#pragma unroll
            for (int mt = 0; mt < 2; ++mt) {
                const int mr = wm*32 + mt*16 + g;
                af[mt][0] = smA[mr*ASTR     + ks*8 + tig];
                af[mt][1] = smA[(mr+8)*ASTR + ks*8 + tig];
                af[mt][2] = smA[mr*ASTR     + ks*8 + tig + 4];
                af[mt][3] = smA[(mr+8)*ASTR + ks*8 + tig + 4];
            }
#pragma unroll
            for (int nt = 0; nt < 8; ++nt) {
                const int nr = wn*64 + nt*8 + g;
                uint32_t bf[2];
                bf[0] = smB[nr*ASTR + ks*8 + tig];
                bf[1] = smB[nr*ASTR + ks*8 + tig + 4];
                mma_tf32(acc[0][nt], af[0], bf);
                mma_tf32(acc[1][nt], af[1], bf);
            }
        }
    }

    // epilogue: bias + write (c0,c1)@row m, (c2,c3)@row m+8, cols n..n+1
#pragma unroll
    for (int mt = 0; mt < 2; ++mt) {
        const int m = m0 + wm*32 + mt*16 + g;
#pragma unroll
        for (int nt = 0; nt < 8; ++nt) {
            const int n = n0 + wn*64 + nt*8 + 2*tig;
            const float2 bv = *(const float2*)(bias + n);
            float2 v0 = { acc[mt][nt][0] + bv.x, acc[mt][nt][1] + bv.y };
            float2 v1 = { acc[mt][nt][2] + bv.x, acc[mt][nt][3] + bv.y };
            if (scatter) {
                const int h = n >> 6, d = n & 63;
                const int bi = m >> 11, s = m & (SEQ - 1);
                float* base = out + (((size_t)bi*NH + h)*SEQ) * DH + d;
                *(float2*)(base + (size_t)s*DH)       = v0;
                *(float2*)(base + (size_t)(s+8)*DH)   = v1;
            } else {
                *(float2*)(out + (size_t)m*D_MODEL + n)     = v0;
                *(float2*)(out + (size_t)(m+8)*D_MODEL + n) = v1;
            }
        }
    }
}

// =====================================================================
// Flash attention with tf32 mma.sync
//   CTA: 256 thr (8 warps), q-tile 128 rows (16/warp), kv-tile 64
//   smem: QP[128][68] (Q, overlaid by P after frag hoist), Ks[64][68], Vs[64][68]
// =====================================================================
#define QSTR 68
#define ATTN_SMEM_BYTES ((128*QSTR + 64*QSTR + 64*QSTR) * 4)

__global__ __launch_bounds__(256) void attn_mma(const int* __restrict__ mask)
{
    extern __shared__ uint32_t sm[];
    uint32_t* QP = sm;                  // [128][68]
    uint32_t* Ks = QP + 128*QSTR;       // [64][68]
    uint32_t* Vs = Ks + 64*QSTR;        // [64][68]

    const int qt = blockIdx.x, h = blockIdx.y, b = blockIdx.z;
    const int tid = threadIdx.x, wid = tid >> 5, lane = tid & 31;
    const int g = lane >> 2, tig = lane & 3;

    const size_t bh = ((size_t)b*NH + h)*SEQ*DH;
    const float* Qg = g_qh + bh + (size_t)qt*128*DH;
    const float* Kg = g_kh + bh;
    const float* Vg = g_vh + bh;

    // stage Q (tf32): 128*64 floats = 2048 float4 slots / 256 thr = 8 each
#pragma unroll
    for (int r = 0; r < 8; ++r) {
        const int slot = tid + r*256;
        const int row = slot >> 4, c4 = (slot & 15) * 4;
        const float4 v = *(const float4*)(Qg + (size_t)row*DH + c4);
        uint32_t* p = QP + row*QSTR + c4;
        p[0]=f2tf32(v.x); p[1]=f2tf32(v.y); p[2]=f2tf32(v.z); p[3]=f2tf32(v.w);
    }
    __syncthreads();

    // hoist Q fragments (rows r0, r0+8) for all 8 ksteps; QP rows of this warp
    // are afterwards reused as the P buffer (warp-private -> no barrier needed)
    const int r0 = wid*16 + g;
    uint32_t aQ[8][4];
#pragma unroll
    for (int ks = 0; ks < 8; ++ks) {
        aQ[ks][0] = QP[r0*QSTR     + ks*8 + tig];
        aQ[ks][1] = QP[(r0+8)*QSTR + ks*8 + tig];
        aQ[ks][2] = QP[r0*QSTR     + ks*8 + tig + 4];
        aQ[ks][3] = QP[(r0+8)*QSTR + ks*8 + tig + 4];
    }

    float m_i[2] = {-1e30f, -1e30f}, l_i[2] = {0.f, 0.f};
    float o[8][4];
#pragma unroll
    for (int nt = 0; nt < 8; ++nt)
#pragma unroll
        for (int i = 0; i < 4; ++i) o[nt][i] = 0.f;

    const int qrow0 = qt*128 + r0;
    const int* mrow0 = mask + ((size_t)b*SEQ + qrow0)*SEQ;
    const int* mrow1 = mrow0 + 8*SEQ;

    for (int kt = 0; kt < SEQ/64; ++kt) {
        __syncthreads();   // all warps done with Ks/Vs of previous tile
        // stage K,V tile: 64*64 floats = 1024 f4 slots / 256 thr = 4 each
#pragma unroll
        for (int r = 0; r < 4; ++r) {
            const int slot = tid + r*256;
            const int row = slot >> 4, c4 = (slot & 15) * 4;
            const float4 kv = *(const float4*)(Kg + (size_t)(kt*64+row)*DH + c4);
            const float4 vv = *(const float4*)(Vg + (size_t)(kt*64+row)*DH + c4);
            uint32_t* pk = Ks + row*QSTR + c4;
            pk[0]=f2tf32(kv.x); pk[1]=f2tf32(kv.y); pk[2]=f2tf32(kv.z); pk[3]=f2tf32(kv.w);
            uint32_t* pv = Vs + row*QSTR + c4;
            pv[0]=f2tf32(vv.x); pv[1]=f2tf32(vv.y); pv[2]=f2tf32(vv.z); pv[3]=f2tf32(vv.w);
        }
        __syncthreads();

        // S = Q K^T  (16 rows x 64 keys per warp)
        float s[8][4];
#pragma unroll
        for (int nt = 0; nt < 8; ++nt) {
            s[nt][0]=0.f; s[nt][1]=0.f; s[nt][2]=0.f; s[nt][3]=0.f;
#pragma unroll
            for (int ks = 0; ks < 8; ++ks) {
                uint32_t bf[2];
                bf[0] = Ks[(nt*8+g)*QSTR + ks*8 + tig];
                bf[1] = Ks[(nt*8+g)*QSTR + ks*8 + tig + 4];
                mma_tf32(s[nt], aQ[ks], bf);
            }
        }

        // scale + mask (exact -10000 semantics)
#pragma unroll
        for (int nt = 0; nt < 8; ++nt) {
            const int c = kt*64 + nt*8 + 2*tig;
            const int2 mv0 = *(const int2*)(mrow0 + c);
            const int2 mv1 = *(const int2*)(mrow1 + c);
            s[nt][0] = mv0.x ? s[nt][0]*0.125f : -10000.f;
            s[nt][1] = mv0.y ? s[nt][1]*0.125f : -10000.f;
            s[nt][2] = mv1.x ? s[nt][2]*0.125f : -10000.f;
            s[nt][3] = mv1.y ? s[nt][3]*0.125f : -10000.f;
        }

        // online softmax: row0 = (c0,c1), row1 = (c2,c3); 4 lanes share a row
        float mx0 = -1e30f, mx1 = -1e30f;
#pragma unroll
        for (int nt = 0; nt < 8; ++nt) {
            mx0 = fmaxf(mx0, fmaxf(s[nt][0], s[nt][1]));
            mx1 = fmaxf(mx1, fmaxf(s[nt][2], s[nt][3]));
        }
        mx0 = fmaxf(mx0, __shfl_xor_sync(0xffffffffu, mx0, 1));
        mx0 = fmaxf(mx0, __shfl_xor_sync(0xffffffffu, mx0, 2));
        mx1 = fmaxf(mx1, __shfl_xor_sync(0xffffffffu, mx1, 1));
        mx1 = fmaxf(mx1, __shfl_xor_sync(0xffffffffu, mx1, 2));
        const float mn0 = fmaxf(m_i[0], mx0);
        const float mn1 = fmaxf(m_i[1], mx1);
        float sum0 = 0.f, sum1 = 0.f;
#pragma unroll
        for (int nt = 0; nt < 8; ++nt) {
            s[nt][0] = __expf(s[nt][0] - mn0); sum0 += s[nt][0];
            s[nt][1] = __expf(s[nt][1] - mn0); sum0 += s[nt][1];
            s[nt][2] = __expf(s[nt][2] - mn1); sum1 += s[nt][2];
            s[nt][3] = __expf(s[nt][3] - mn1); sum1 += s[nt][3];
        }
        sum0 += __shfl_xor_sync(0xffffffffu, sum0, 1);
        sum0 += __shfl_xor_sync(0xffffffffu, sum0, 2);
        sum1 += __shfl_xor_sync(0xffffffffu, sum1, 1);
        sum1 += __shfl_xor_sync(0xffffffffu, sum1, 2);
        const float corr0 = __expf(m_i[0] - mn0);
        const float corr1 = __expf(m_i[1] - mn1);
        l_i[0] = l_i[0]*corr0 + sum0;  m_i[0] = mn0;
        l_i[1] = l_i[1]*corr1 + sum1;  m_i[1] = mn1;
#pragma unroll
        for (int nt = 0; nt < 8; ++nt) {
            o[nt][0] *= corr0; o[nt][1] *= corr0;
            o[nt][2] *= corr1; o[nt][3] *= corr1;
        }

        // P -> smem (tf32), warp-private rows
#pragma unroll
        for (int nt = 0; nt < 8; ++nt) {
            const int c = nt*8 + 2*tig;
            QP[r0*QSTR + c]         = f2tf32(s[nt][0]);
            QP[r0*QSTR + c + 1]     = f2tf32(s[nt][1]);
            QP[(r0+8)*QSTR + c]     = f2tf32(s[nt][2]);
            QP[(r0+8)*QSTR + c + 1] = f2tf32(s[nt][3]);
        }
        __syncwarp();

        // O += P V
#pragma unroll
        for (int ks = 0; ks < 8; ++ks) {
            uint32_t aP[4];
            aP[0] = QP[r0*QSTR     + ks*8 + tig];
            aP[1] = QP[(r0+8)*QSTR + ks*8 + tig];
            aP[2] = QP[r0*QSTR     + ks*8 + tig + 4];
            aP[3] = QP[(r0+8)*QSTR + ks*8 + tig + 4];
#pragma unroll
            for (int nt = 0; nt < 8; ++nt) {
                uint32_t bf[2];
                bf[0] = Vs[(ks*8+tig)*QSTR   + nt*8 + g];
                bf[1] = Vs[(ks*8+tig+4)*QSTR + nt*8 + g];
                mma_tf32(o[nt], aP, bf);
            }
        }
    }

    // normalize + write [b,s,h*dh]
    const float inv0 = 1.f / l_i[0], inv1 = 1.f / l_i[1];
    float* out0 = g_attn + ((size_t)b*SEQ + qrow0)*D_MODEL + h*DH;
    float* out1 = out0 + (size_t)8*D_MODEL;
#pragma unroll
    for (int nt = 0; nt < 8; ++nt) {
        const int c = nt*8 + 2*tig;
        float2 v0 = { o[nt][0]*inv0, o[nt][1]*inv0 };
        float2 v1 = { o[nt][2]*inv1, o[nt][3]*inv1 };
        *(float2*)(out0 + c) = v0;
        *(float2*)(out1 + c) = v1;
    }
}

// ================= launch =================
extern "C" void kernel_launch(void* const* d_in, const int* in_sizes, int n_in,
                              void* d_out, int out_size)
{
    (void)in_sizes; (void)n_in; (void)out_size;
    const float* q  = (const float*)d_in[0];
    const float* k  = (const float*)d_in[1];
    const float* v  = (const float*)d_in[2];
    const int* mask = (const int*)d_in[3];
    const float* Wq = (const float*)d_in[4];
    const float* bq = (const float*)d_in[5];
    const float* Wk = (const float*)d_in[6];
    const float* bk = (const float*)d_in[7];
    const float* Wv = (const float*)d_in[8];
    const float* bv = (const float*)d_in[9];
    const float* Wo = (const float*)d_in[10];
    const float* bo = (const float*)d_in[11];
    float* out = (float*)d_out;

    dim3 ggrid(D_MODEL/128, MTOT/128, 1);   // 8 x 32
    tc_gemm<<<ggrid, 256>>>(q, Wq, bq, nullptr, 0);
    tc_gemm<<<ggrid, 256>>>(k, Wk, bk, nullptr, 1);
    tc_gemm<<<ggrid, 256>>>(v, Wv, bv, nullptr, 2);

    cudaFuncSetAttribute(attn_mma, cudaFuncAttributeMaxDynamicSharedMemorySize, ATTN_SMEM_BYTES);
    attn_mma<<<dim3(SEQ/128, NH, BATCH), 256, ATTN_SMEM_BYTES>>>(mask);

    tc_gemm<<<ggrid, 256>>>(nullptr, Wo, bo, out, 3);
}

// round 4
// speedup vs baseline: 2.7032x; 1.0777x over previous
#include <cuda_runtime.h>
#include <cstdint>

#define D_MODEL 1024
#define NH      16
#define DH      64
#define BATCH   2
#define SEQ     2048
#define MTOT    (BATCH*SEQ)   // 4096
#define KDIM    1024

// ---------------- scratch (allocation-free) ----------------
__device__ float g_qh[(size_t)BATCH*NH*SEQ*DH];     // [b,h,s,dh]
__device__ float g_kh[(size_t)BATCH*NH*SEQ*DH];
__device__ float g_vh[(size_t)BATCH*NH*SEQ*DH];
__device__ float g_attn[(size_t)BATCH*SEQ*D_MODEL]; // [b,s,h*dh]

// =====================================================================
// helpers
// =====================================================================
__device__ __forceinline__ uint32_t f2tf32(float f) {
    uint32_t r;
    asm("cvt.rna.tf32.f32 %0, %1;" : "=r"(r) : "f"(f));
    return r;
}

// D += A(16x8,row) * B(8x8,col)  tf32
__device__ __forceinline__ void mma_tf32(float c[4], const uint32_t a[4], const uint32_t b[2]) {
    asm volatile(
        "mma.sync.aligned.m16n8k8.row.col.f32.tf32.tf32.f32 "
        "{%0,%1,%2,%3}, {%4,%5,%6,%7}, {%8,%9}, {%0,%1,%2,%3};"
        : "+f"(c[0]), "+f"(c[1]), "+f"(c[2]), "+f"(c[3])
        : "r"(a[0]), "r"(a[1]), "r"(a[2]), "r"(a[3]), "r"(b[0]), "r"(b[1]));
}

// =====================================================================
// GEMM mainloop (tf32 mma.sync): acc[2][8][4] += X[128,K] @ W[128,K]^T tile
//   256 thr, warp grid 4(m)x2(n), warp tile 32x64, BK=32
// =====================================================================
#define GBK  32
#define ASTR 36   // BK + 4 pad

__device__ __forceinline__ void gemm_core(
    const float* __restrict__ gA, const float* __restrict__ gB,
    uint32_t* smA, uint32_t* smB, float acc[2][8][4])
{
    const int tid = threadIdx.x, wid = tid >> 5, lane = tid & 31;
    const int g = lane >> 2, tig = lane & 3;
    const int wm = wid >> 1, wn = wid & 1;

    int srow[4];
    const int scol = (tid & 7) * 4;
#pragma unroll
    for (int r = 0; r < 4; ++r) srow[r] = (tid + r*256) >> 3;

    float4 pa[4], pb[4];
#pragma unroll
    for (int r = 0; r < 4; ++r) {
        pa[r] = *(const float4*)(gA + (size_t)srow[r]*KDIM + scol);
        pb[r] = *(const float4*)(gB + (size_t)srow[r]*KDIM + scol);
    }

    const int NKT = KDIM / GBK;   // 32
    for (int kt = 0; kt < NKT; ++kt) {
        __syncthreads();
#pragma unroll
        for (int r = 0; r < 4; ++r) {
            uint32_t* pA = smA + srow[r]*ASTR + scol;
            pA[0]=f2tf32(pa[r].x); pA[1]=f2tf32(pa[r].y); pA[2]=f2tf32(pa[r].z); pA[3]=f2tf32(pa[r].w);
            uint32_t* pB = smB + srow[r]*ASTR + scol;
            pB[0]=f2tf32(pb[r].x); pB[1]=f2tf32(pb[r].y); pB[2]=f2tf32(pb[r].z); pB[3]=f2tf32(pb[r].w);
        }
        __syncthreads();
        if (kt + 1 < NKT) {
            const int k1 = (kt + 1) * GBK;
#pragma unroll
            for (int r = 0; r < 4; ++r) {
                pa[r] = *(const float4*)(gA + (size_t)srow[r]*KDIM + k1 + scol);
                pb[r] = *(const float4*)(gB + (size_t)srow[r]*KDIM + k1 + scol);
            }
        }
#pragma unroll
        for (int ks = 0; ks < 4; ++ks) {
            uint32_t af[2][4];
#pragma unroll
            for (int mt = 0; mt < 2; ++mt) {
                const int mr = wm*32 + mt*16 + g;
                af[mt][0] = smA[mr*ASTR     + ks*8 + tig];
                af[mt][1] = smA[(mr+8)*ASTR + ks*8 + tig];
                af[mt][2] = smA[mr*ASTR     + ks*8 + tig + 4];
                af[mt][3] = smA[(mr+8)*ASTR + ks*8 + tig + 4];
            }
#pragma unroll
            for (int nt = 0; nt < 8; ++nt) {
                const int nr = wn*64 + nt*8 + g;
                uint32_t bf[2];
                bf[0] = smB[nr*ASTR + ks*8 + tig];
                bf[1] = smB[nr*ASTR + ks*8 + tig + 4];
                mma_tf32(acc[0][nt], af[0], bf);
                mma_tf32(acc[1][nt], af[1], bf);
            }
        }
    }
}

// ---- fused Q/K/V projection (grid.z selects), scatter to head layout ----
__global__ __launch_bounds__(256, 2) void proj_gemm(
    const float* __restrict__ xq, const float* __restrict__ xk, const float* __restrict__ xv,
    const float* __restrict__ Wq, const float* __restrict__ Wk, const float* __restrict__ Wv,
    const float* __restrict__ bq, const float* __restrict__ bk, const float* __restrict__ bv)
{
    __shared__ uint32_t smA[128*ASTR];
    __shared__ uint32_t smB[128*ASTR];
    const int z = blockIdx.z;
    const float* X    = (z == 0) ? xq : (z == 1) ? xk : xv;
    const float* W    = (z == 0) ? Wq : (z == 1) ? Wk : Wv;
    const float* bias = (z == 0) ? bq : (z == 1) ? bk : bv;
    float* out        = (z == 0) ? g_qh : (z == 1) ? g_kh : g_vh;

    const int m0 = blockIdx.y * 128, n0 = blockIdx.x * 128;
    float acc[2][8][4] = {};
    gemm_core(X + (size_t)m0*KDIM, W + (size_t)n0*KDIM, smA, smB, acc);

    const int tid = threadIdx.x, wid = tid >> 5, lane = tid & 31;
    const int g = lane >> 2, tig = lane & 3;
    const int wm = wid >> 1, wn = wid & 1;
#pragma unroll
    for (int mt = 0; mt < 2; ++mt) {
        const int m = m0 + wm*32 + mt*16 + g;
        const int bi = m >> 11, s = m & (SEQ - 1);
#pragma unroll
        for (int nt = 0; nt < 8; ++nt) {
            const int n = n0 + wn*64 + nt*8 + 2*tig;
            const float2 bv2 = *(const float2*)(bias + n);
            float2 v0 = { acc[mt][nt][0] + bv2.x, acc[mt][nt][1] + bv2.y };
            float2 v1 = { acc[mt][nt][2] + bv2.x, acc[mt][nt][3] + bv2.y };
            const int h = n >> 6, d = n & 63;
            float* base = out + (((size_t)bi*NH + h)*SEQ) * DH + d;
            *(float2*)(base + (size_t)s*DH)     = v0;
            *(float2*)(base + (size_t)(s+8)*DH) = v1;
        }
    }
}

// ---- output projection: d_out = g_attn @ Wo^T + bo ----
__global__ __launch_bounds__(256, 2) void out_gemm(
    const float* __restrict__ Wo, const float* __restrict__ bo, float* __restrict__ out)
{
    __shared__ uint32_t smA[128*ASTR];
    __shared__ uint32_t smB[128*ASTR];
    const int m0 = blockIdx.y * 128, n0 = blockIdx.x * 128;
    float acc[2][8][4] = {};
    gemm_core(g_attn + (size_t)m0*KDIM, Wo + (size_t)n0*KDIM, smA, smB, acc);

    const int tid = threadIdx.x, wid = tid >> 5, lane = tid & 31;
    const int g = lane >> 2, tig = lane & 3;
    const int wm = wid >> 1, wn = wid & 1;
#pragma unroll
    for (int mt = 0; mt < 2; ++mt) {
        const int m = m0 + wm*32 + mt*16 + g;
#pragma unroll
        for (int nt = 0; nt < 8; ++nt) {
            const int n = n0 + wn*64 + nt*8 + 2*tig;
            const float2 bv2 = *(const float2*)(bo + n);
            float2 v0 = { acc[mt][nt][0] + bv2.x, acc[mt][nt][1] + bv2.y };
            float2 v1 = { acc[mt][nt][2] + bv2.x, acc[mt][nt][3] + bv2.y };
            *(float2*)(out + (size_t)m*D_MODEL + n)     = v0;
            *(float2*)(out + (size_t)(m+8)*D_MODEL + n) = v1;
        }
    }
}

// =====================================================================
// Flash attention (tf32 mma.sync), 2 CTAs/SM target
//   CTA: 256 thr (8 warps), q-tile 128 rows (16/warp), kv-tile 64
//   smem: Qs[128][68], Ks[64][68], Vs[64][68], Ps[128][68]
//   Q fragments re-loaded from smem per tile (saves 32 regs vs hoisting).
// =====================================================================
#define QSTR 68
#define ATTN_SMEM_BYTES ((128*QSTR + 64*QSTR + 64*QSTR + 128*QSTR) * 4)
#define LOG2E    1.4426950408889634f
#define MSK_NEG  (-10000.0f * LOG2E)
#define SCL_L2E  (0.125f * LOG2E)

__global__ __launch_bounds__(256, 2) void attn_mma(const int* __restrict__ mask)
{
    extern __shared__ uint32_t sm[];
    uint32_t* Qs = sm;                  // [128][68]
    uint32_t* Ks = Qs + 128*QSTR;       // [64][68]
    uint32_t* Vs = Ks + 64*QSTR;        // [64][68]
    uint32_t* Ps = Vs + 64*QSTR;        // [128][68]

    const int qt = blockIdx.x, h = blockIdx.y, b = blockIdx.z;
    const int tid = threadIdx.x, wid = tid >> 5, lane = tid & 31;
    const int g = lane >> 2, tig = lane & 3;

    const size_t bh = ((size_t)b*NH + h)*SEQ*DH;
    const float* Qg = g_qh + bh + (size_t)qt*128*DH;
    const float* Kg = g_kh + bh;
    const float* Vg = g_vh + bh;

    // stage Q (tf32): 128*64 floats = 2048 float4 slots / 256 thr = 8 each
#pragma unroll
    for (int r = 0; r < 8; ++r) {
        const int slot = tid + r*256;
        const int row = slot >> 4, c4 = (slot & 15) * 4;
        const float4 v = *(const float4*)(Qg + (size_t)row*DH + c4);
        uint32_t* p = Qs + row*QSTR + c4;
        p[0]=f2tf32(v.x); p[1]=f2tf32(v.y); p[2]=f2tf32(v.z); p[3]=f2tf32(v.w);
    }

    const int r0 = wid*16 + g;
    float m_i[2] = {-1e30f, -1e30f}, l_i[2] = {0.f, 0.f};
    float o[8][4];
#pragma unroll
    for (int nt = 0; nt < 8; ++nt)
#pragma unroll
        for (int i = 0; i < 4; ++i) o[nt][i] = 0.f;

    const int qrow0 = qt*128 + r0;
    const int* mrow0 = mask + ((size_t)b*SEQ + qrow0)*SEQ;
    const int* mrow1 = mrow0 + 8*SEQ;

    for (int kt = 0; kt < SEQ/64; ++kt) {
        __syncthreads();   // prev tile fully consumed (and Q staged on kt=0)
        // stage K,V tile: 64*64 floats = 1024 f4 slots / 256 thr = 4 each
#pragma unroll
        for (int r = 0; r < 4; ++r) {
            const int slot = tid + r*256;
            const int row = slot >> 4, c4 = (slot & 15) * 4;
            const float4 kv = *(const float4*)(Kg + (size_t)(kt*64+row)*DH + c4);
            const float4 vv = *(const float4*)(Vg + (size_t)(kt*64+row)*DH + c4);
            uint32_t* pk = Ks + row*QSTR + c4;
            pk[0]=f2tf32(kv.x); pk[1]=f2tf32(kv.y); pk[2]=f2tf32(kv.z); pk[3]=f2tf32(kv.w);
            uint32_t* pv = Vs + row*QSTR + c4;
            pv[0]=f2tf32(vv.x); pv[1]=f2tf32(vv.y); pv[2]=f2tf32(vv.z); pv[3]=f2tf32(vv.w);
        }
        __syncthreads();

        // S = Q K^T  (16 rows x 64 keys per warp); Q frags re-loaded per kstep
        float s[8][4];
#pragma unroll
        for (int nt = 0; nt < 8; ++nt) { s[nt][0]=0.f; s[nt][1]=0.f; s[nt][2]=0.f; s[nt][3]=0.f; }
#pragma unroll
        for (int ks = 0; ks < 8; ++ks) {
            uint32_t aQ[4];
            aQ[0] = Qs[r0*QSTR     + ks*8 + tig];
            aQ[1] = Qs[(r0+8)*QSTR + ks*8 + tig];
            aQ[2] = Qs[r0*QSTR     + ks*8 + tig + 4];
            aQ[3] = Qs[(r0+8)*QSTR + ks*8 + tig + 4];
#pragma unroll
            for (int nt = 0; nt < 8; ++nt) {
                uint32_t bf[2];
                bf[0] = Ks[(nt*8+g)*QSTR + ks*8 + tig];
                bf[1] = Ks[(nt*8+g)*QSTR + ks*8 + tig + 4];
                mma_tf32(s[nt], aQ, bf);
            }
        }

        // scale+log2e fold + mask (masked -> -10000*log2e, exact semantics)
#pragma unroll
        for (int nt = 0; nt < 8; ++nt) {
            const int c = kt*64 + nt*8 + 2*tig;
            const int2 mv0 = *(const int2*)(mrow0 + c);
            const int2 mv1 = *(const int2*)(mrow1 + c);
            s[nt][0] = mv0.x ? s[nt][0]*SCL_L2E : MSK_NEG;
            s[nt][1] = mv0.y ? s[nt][1]*SCL_L2E : MSK_NEG;
            s[nt][2] = mv1.x ? s[nt][2]*SCL_L2E : MSK_NEG;
            s[nt][3] = mv1.y ? s[nt][3]*SCL_L2E : MSK_NEG;
        }

        // online softmax in log2 domain: row0=(c0,c1), row1=(c2,c3)
        float mx0 = -1e30f, mx1 = -1e30f;
#pragma unroll
        for (int nt = 0; nt < 8; ++nt) {
            mx0 = fmaxf(mx0, fmaxf(s[nt][0], s[nt][1]));
            mx1 = fmaxf(mx1, fmaxf(s[nt][2], s[nt][3]));
        }
        mx0 = fmaxf(mx0, __shfl_xor_sync(0xffffffffu, mx0, 1));
        mx0 = fmaxf(mx0, __shfl_xor_sync(0xffffffffu, mx0, 2));
        mx1 = fmaxf(mx1, __shfl_xor_sync(0xffffffffu, mx1, 1));
        mx1 = fmaxf(mx1, __shfl_xor_sync(0xffffffffu, mx1, 2));
        const float mn0 = fmaxf(m_i[0], mx0);
        const float mn1 = fmaxf(m_i[1], mx1);
        float sum0 = 0.f, sum1 = 0.f;
#pragma unroll
        for (int nt = 0; nt < 8; ++nt) {
            s[nt][0] = exp2f(s[nt][0] - mn0); sum0 += s[nt][0];
            s[nt][1] = exp2f(s[nt][1] - mn0); sum0 += s[nt][1];
            s[nt][2] = exp2f(s[nt][2] - mn1); sum1 += s[nt][2];
            s[nt][3] = exp2f(s[nt][3] - mn1); sum1 += s[nt][3];
        }
        sum0 += __shfl_xor_sync(0xffffffffu, sum0, 1);
        sum0 += __shfl_xor_sync(0xffffffffu, sum0, 2);
        sum1 += __shfl_xor_sync(0xffffffffu, sum1, 1);
        sum1 += __shfl_xor_sync(0xffffffffu, sum1, 2);
        const float corr0 = exp2f(m_i[0] - mn0);
        const float corr1 = exp2f(m_i[1] - mn1);
        l_i[0] = l_i[0]*corr0 + sum0;  m_i[0] = mn0;
        l_i[1] = l_i[1]*corr1 + sum1;  m_i[1] = mn1;
#pragma unroll
        for (int nt = 0; nt < 8; ++nt) {
            o[nt][0] *= corr0; o[nt][1] *= corr0;
            o[nt][2] *= corr1; o[nt][3] *= corr1;
        }

        // P -> smem (tf32), warp-private rows
#pragma unroll
        for (int nt = 0; nt < 8; ++nt) {
            const int c = nt*8 + 2*tig;
            Ps[r0*QSTR + c]         = f2tf32(s[nt][0]);
            Ps[r0*QSTR + c + 1]     = f2tf32(s[nt][1]);
            Ps[(r0+8)*QSTR + c]     = f2tf32(s[nt][2]);
            Ps[(r0+8)*QSTR + c + 1] = f2tf32(s[nt][3]);
        }
        __syncwarp();

        // O += P V
#pragma unroll
        for (int ks = 0; ks < 8; ++ks) {
            uint32_t aP[4];
            aP[0] = Ps[r0*QSTR     + ks*8 + tig];
            aP[1] = Ps[(r0+8)*QSTR + ks*8 + tig];
            aP[2] = Ps[r0*QSTR     + ks*8 + tig + 4];
            aP[3] = Ps[(r0+8)*QSTR + ks*8 + tig + 4];
#pragma unroll
            for (int nt = 0; nt < 8; ++nt) {
                uint32_t bf[2];
                bf[0] = Vs[(ks*8+tig)*QSTR   + nt*8 + g];
                bf[1] = Vs[(ks*8+tig+4)*QSTR + nt*8 + g];
                mma_tf32(o[nt], aP, bf);
            }
        }
    }

    // normalize + write [b,s,h*dh]
    const float inv0 = 1.f / l_i[0], inv1 = 1.f / l_i[1];
    float* out0 = g_attn + ((size_t)b*SEQ + qrow0)*D_MODEL + h*DH;
    float* out1 = out0 + (size_t)8*D_MODEL;
#pragma unroll
    for (int nt = 0; nt < 8; ++nt) {
        const int c = nt*8 + 2*tig;
        float2 v0 = { o[nt][0]*inv0, o[nt][1]*inv0 };
        float2 v1 = { o[nt][2]*inv1, o[nt][3]*inv1 };
        *(float2*)(out0 + c) = v0;
        *(float2*)(out1 + c) = v1;
    }
}

// ================= launch =================
extern "C" void kernel_launch(void* const* d_in, const int* in_sizes, int n_in,
                              void* d_out, int out_size)
{
    (void)in_sizes; (void)n_in; (void)out_size;
    const float* q  = (const float*)d_in[0];
    const float* k  = (const float*)d_in[1];
    const float* v  = (const float*)d_in[2];
    const int* mask = (const int*)d_in[3];
    const float* Wq = (const float*)d_in[4];
    const float* bq = (const float*)d_in[5];
    const float* Wk = (const float*)d_in[6];
    const float* bk = (const float*)d_in[7];
    const float* Wv = (const float*)d_in[8];
    const float* bv = (const float*)d_in[9];
    const float* Wo = (const float*)d_in[10];
    const float* bo = (const float*)d_in[11];
    float* out = (float*)d_out;

    proj_gemm<<<dim3(D_MODEL/128, MTOT/128, 3), 256>>>(q, k, v, Wq, Wk, Wv, bq, bk, bv);

    cudaFuncSetAttribute(attn_mma, cudaFuncAttributeMaxDynamicSharedMemorySize, ATTN_SMEM_BYTES);
    attn_mma<<<dim3(SEQ/128, NH, BATCH), 256, ATTN_SMEM_BYTES>>>(mask);

    out_gemm<<<dim3(D_MODEL/128, MTOT/128, 1), 256>>>(Wo, bo, out);
}